// round 5
// baseline (speedup 1.0000x reference)
#include <cuda_runtime.h>
#include <math.h>

// GAT layer, algebraically folded:
//   Wn = attn1_w[:,64:] @ align_w  (16x64), Wt = attn1_w[:,:64] @ align_w
//   cb = (attn1_w[:,:64]+attn1_w[:,64:]) @ align_b + attn1_b
//   e_n = leaky(attn2 @ relu(Wn x_n + Wt x_t + cb) + b2); a = softmax(e)
//   out = elu(align_w @ (sum_n a_n x_n) + align_b)
//
// R4: Wn/cb/attn2 live in __constant__ (LDC, off the LSU pipe); phase-2 GEMM
// retiled to lane=(row-slot 0..15, h-half 0..1) so x smem redundancy is 2x
// instead of 4x and weight smem traffic is zero.

#define NGRP  16384
#define GRID  1480

typedef unsigned long long ull;

__device__ float WnP_g[1024];   // folded Wn, [c][h]
__device__ float WtP_g[1024];   // folded Wt, [c][h]
__device__ float CBP_g[16];

__constant__ float cWn[1024];   // [c][16h]
__constant__ float cCB[16];
__constant__ float cA2[16];
__constant__ float cA2B[1];

__device__ __forceinline__ ull splat2(float a) {
    ull r; asm("mov.b64 %0, {%1, %1};" : "=l"(r) : "f"(a)); return r;
}
__device__ __forceinline__ void fma2(ull& acc, ull a, ull b) {
    asm("fma.rn.f32x2 %0, %1, %2, %0;" : "+l"(acc) : "l"(a), "l"(b));
}
__device__ __forceinline__ ull add2(ull a, ull b) {
    ull r; asm("add.rn.f32x2 %0, %1, %2;" : "=l"(r) : "l"(a), "l"(b)); return r;
}
__device__ __forceinline__ float2 unpack2(ull v) {
    float2 r; asm("mov.b64 {%0, %1}, %2;" : "=f"(r.x), "=f"(r.y) : "l"(v)); return r;
}

// ---------------- prologue: fold weights ----------------
__global__ void prep_kernel(const float* __restrict__ align_w,
                            const float* __restrict__ align_b,
                            const float* __restrict__ a1w,
                            const float* __restrict__ a1b) {
    int idx = blockIdx.x * blockDim.x + threadIdx.x;
    if (idx < 1024) {
        int c = idx >> 4, h = idx & 15;
        float st = 0.f, sn = 0.f;
        for (int d = 0; d < 64; d++) {
            float aw = align_w[d * 64 + c];
            st = fmaf(a1w[h * 128 + d],      aw, st);
            sn = fmaf(a1w[h * 128 + 64 + d], aw, sn);
        }
        WtP_g[c * 16 + h] = st;
        WnP_g[c * 16 + h] = sn;
    } else if (idx < 1040) {
        int h = idx - 1024;
        float s = 0.f;
        for (int d = 0; d < 64; d++)
            s += (a1w[h * 128 + d] + a1w[h * 128 + 64 + d]) * align_b[d];
        CBP_g[h] = s + a1b[h];
    }
}

// ---------------- main fused kernel ----------------
__global__ __launch_bounds__(128, 5)
void gat_kernel(const float* __restrict__ xt,
                const float* __restrict__ xn,
                const float* __restrict__ align_w,
                const float* __restrict__ align_b,
                float* __restrict__ out) {
    __shared__ __align__(16) float4 xs4[4][576];   // 36 rows x 16 chunks, XOR-swizzled
    __shared__ __align__(16) float  Wt_s[1024];
    __shared__ __align__(8)  float  a_s[4][36];
    __shared__ __align__(16) float  s_s[4][64];
    __shared__ __align__(16) float  part[4][64];

    const int tid  = threadIdx.x;
    const int wid  = tid >> 5;
    const int lane = tid & 31;
    const int rG   = lane & 15;      // row slot
    const int hG   = lane >> 4;      // h half (8 h each)

    for (int i = tid; i < 1024; i += 128) Wt_s[i] = WtP_g[i];

    // phase-5 register cache: align_w half-row per thread
    const int d = tid & 63, half = tid >> 6;
    float ar[32];
#pragma unroll
    for (int i = 0; i < 32; i++) ar[i] = align_w[d * 64 + half * 32 + i];
    const float ab = align_b[d];

    __syncthreads();

    const ulonglong2* cWnV = (const ulonglong2*)cWn;
    const ulonglong2* WtV  = (const ulonglong2*)Wt_s;

    for (int g = blockIdx.x; g < NGRP; g += GRID) {
        const int b = g * 4 + wid;
        float4* xw4 = xs4[wid];
        const float* xw = (const float*)xw4;

        // ---- phase 1: stage x_neigh (rows 0..34) + x_target (row 35), swizzled
        {
            const float4* src4 = (const float4*)xn + (size_t)b * 560;
            const float4* xt4  = (const float4*)xt + (size_t)b * 16;
#pragma unroll
            for (int k = 0; k < 18; k++) {
                int idx = k * 32 + lane;
                float4 v = (idx < 560) ? src4[idx] : xt4[idx - 560];
                int row = idx >> 4, cq = idx & 15;
                xw4[row * 16 + (cq ^ (row & 7))] = v;
            }
        }
        __syncwarp();

        // ---- phase 2: u[row][8h] for rows {rG, rG+16, rG+32?}, weights from constant
        ull u0[4], u1[4], u2v[4];
#pragma unroll
        for (int k = 0; k < 4; k++) { u0[k] = 0ull; u1[k] = 0ull; u2v[k] = 0ull; }

        const bool has2 = (rG < 3);
        const int r0 = rG, r1 = rG + 16;
        const int r2 = has2 ? (rG + 32) : rG;     // discarded if !has2

#pragma unroll 4
        for (int p4 = 0; p4 < 16; p4++) {
            float4 x0 = xw4[r0 * 16 + (p4 ^ (r0 & 7))];
            float4 x1 = xw4[r1 * 16 + (p4 ^ (r1 & 7))];
            float4 x2 = xw4[r2 * 16 + (p4 ^ (r2 & 7))];
#pragma unroll
            for (int cc = 0; cc < 4; cc++) {
                int c = 4 * p4 + cc;
                ulonglong2 wa = cWnV[c * 4 + hG * 2];       // h 0..3 of half
                ulonglong2 wb = cWnV[c * 4 + hG * 2 + 1];   // h 4..7 of half
                float f0 = (cc == 0) ? x0.x : (cc == 1) ? x0.y : (cc == 2) ? x0.z : x0.w;
                float f1 = (cc == 0) ? x1.x : (cc == 1) ? x1.y : (cc == 2) ? x1.z : x1.w;
                float f2 = (cc == 0) ? x2.x : (cc == 1) ? x2.y : (cc == 2) ? x2.z : x2.w;
                ull a0 = splat2(f0), a1 = splat2(f1), a2 = splat2(f2);
                fma2(u0[0], a0, wa.x); fma2(u0[1], a0, wa.y);
                fma2(u0[2], a0, wb.x); fma2(u0[3], a0, wb.y);
                fma2(u1[0], a1, wa.x); fma2(u1[1], a1, wa.y);
                fma2(u1[2], a1, wb.x); fma2(u1[3], a1, wb.y);
                fma2(u2v[0], a2, wa.x); fma2(u2v[1], a2, wa.y);
                fma2(u2v[2], a2, wb.x); fma2(u2v[3], a2, wb.y);
            }
        }

        // ---- target path: ub[8h] = (Wt @ x_t)[hG half] + cb, c split over rG
        ull ub[4];
        {
            float4 xtv = xw4[35 * 16 + (rG ^ 3)];           // 35 & 7 == 3
            ub[0] = 0ull; ub[1] = 0ull; ub[2] = 0ull; ub[3] = 0ull;
#pragma unroll
            for (int cc = 0; cc < 4; cc++) {
                int c = 4 * rG + cc;
                ulonglong2 wa = WtV[c * 4 + hG * 2];
                ulonglong2 wb = WtV[c * 4 + hG * 2 + 1];
                float xc = (cc == 0) ? xtv.x : (cc == 1) ? xtv.y : (cc == 2) ? xtv.z : xtv.w;
                ull a = splat2(xc);
                fma2(ub[0], a, wa.x); fma2(ub[1], a, wa.y);
                fma2(ub[2], a, wb.x); fma2(ub[3], a, wb.y);
            }
#pragma unroll
            for (int m = 1; m <= 8; m <<= 1) {
#pragma unroll
                for (int k = 0; k < 4; k++)
                    ub[k] = add2(ub[k], __shfl_xor_sync(0xffffffffu, ub[k], m));
            }
            const ulonglong2* cbV = (const ulonglong2*)cCB;
            ulonglong2 cb0 = cbV[hG * 2], cb1 = cbV[hG * 2 + 1];
            ub[0] = add2(ub[0], cb0.x); ub[1] = add2(ub[1], cb0.y);
            ub[2] = add2(ub[2], cb1.x); ub[3] = add2(ub[3], cb1.y);
        }

        // ---- phase 3: e per row (dot over this lane's 8 h + shfl over hG), softmax
        float ubf[8];
        {
            float2 t0 = unpack2(ub[0]), t1 = unpack2(ub[1]);
            float2 t2 = unpack2(ub[2]), t3 = unpack2(ub[3]);
            ubf[0] = t0.x; ubf[1] = t0.y; ubf[2] = t1.x; ubf[3] = t1.y;
            ubf[4] = t2.x; ubf[5] = t2.y; ubf[6] = t3.x; ubf[7] = t3.y;
        }
        float a2r[8];
#pragma unroll
        for (int k = 0; k < 8; k++) a2r[k] = cA2[hG * 8 + k];

        float pe0 = 0.f, pe1 = 0.f, pe2 = 0.f;
#pragma unroll
        for (int k = 0; k < 4; k++) {
            float2 v0 = unpack2(u0[k]), v1 = unpack2(u1[k]), v2 = unpack2(u2v[k]);
            pe0 = fmaf(a2r[2*k],   fmaxf(v0.x + ubf[2*k],   0.f), pe0);
            pe0 = fmaf(a2r[2*k+1], fmaxf(v0.y + ubf[2*k+1], 0.f), pe0);
            pe1 = fmaf(a2r[2*k],   fmaxf(v1.x + ubf[2*k],   0.f), pe1);
            pe1 = fmaf(a2r[2*k+1], fmaxf(v1.y + ubf[2*k+1], 0.f), pe1);
            pe2 = fmaf(a2r[2*k],   fmaxf(v2.x + ubf[2*k],   0.f), pe2);
            pe2 = fmaf(a2r[2*k+1], fmaxf(v2.y + ubf[2*k+1], 0.f), pe2);
        }
        pe0 += __shfl_xor_sync(0xffffffffu, pe0, 16);
        pe1 += __shfl_xor_sync(0xffffffffu, pe1, 16);
        pe2 += __shfl_xor_sync(0xffffffffu, pe2, 16);
        const float b2 = cA2B[0];
        float e0 = pe0 + b2; e0 = (e0 > 0.f) ? e0 : 0.2f * e0;
        float e1 = pe1 + b2; e1 = (e1 > 0.f) ? e1 : 0.2f * e1;
        float e2 = pe2 + b2; e2 = (e2 > 0.f) ? e2 : 0.2f * e2;

        float mx = fmaxf(e0, e1);
        if (has2) mx = fmaxf(mx, e2);
#pragma unroll
        for (int m = 1; m <= 8; m <<= 1) mx = fmaxf(mx, __shfl_xor_sync(0xffffffffu, mx, m));

        float ax0 = __expf(e0 - mx), ax1 = __expf(e1 - mx);
        float ax2 = has2 ? __expf(e2 - mx) : 0.f;
        float sum = ax0 + ax1 + ax2;
#pragma unroll
        for (int m = 1; m <= 8; m <<= 1) sum += __shfl_xor_sync(0xffffffffu, sum, m);
        float rinv = 1.0f / sum;

        if (hG == 0) {
            a_s[wid][rG]      = ax0 * rinv;
            a_s[wid][rG + 16] = ax1 * rinv;
            if (has2)     a_s[wid][rG + 32] = ax2 * rinv;
            if (rG == 3)  a_s[wid][35] = 0.f;   // target row pad -> 0
        }
        __syncwarp();

        // ---- phase 4: s[c] = sum_n a_n x_n[c]   (lane owns c = 2*lane, 2*lane+1)
        float slo = 0.f, shi = 0.f;
#pragma unroll 6
        for (int q = 0; q < 18; q++) {
            float2 av = *(const float2*)&a_s[wid][2 * q];
            int r0q = 2 * q, r1q = r0q + 1;
            float2 x0 = *(const float2*)&xw[r0q * 64 + (((lane >> 1) ^ (r0q & 7)) << 2) + ((lane & 1) << 1)];
            float2 x1 = *(const float2*)&xw[r1q * 64 + (((lane >> 1) ^ (r1q & 7)) << 2) + ((lane & 1) << 1)];
            slo = fmaf(av.x, x0.x, slo); shi = fmaf(av.x, x0.y, shi);
            slo = fmaf(av.y, x1.x, slo); shi = fmaf(av.y, x1.y, shi);
        }
        *(float2*)&s_s[wid][2 * lane] = make_float2(slo, shi);
        __syncthreads();

        // ---- phase 5: out = elu(align_w @ s + align_b), block-coop, ar in regs
        float acc[4];
#pragma unroll
        for (int bb = 0; bb < 4; bb++) {
            float a = 0.f;
            const float4* sp = (const float4*)&s_s[bb][half * 32];
#pragma unroll
            for (int i4 = 0; i4 < 8; i4++) {
                float4 sv = sp[i4];
                a = fmaf(ar[i4 * 4 + 0], sv.x, a);
                a = fmaf(ar[i4 * 4 + 1], sv.y, a);
                a = fmaf(ar[i4 * 4 + 2], sv.z, a);
                a = fmaf(ar[i4 * 4 + 3], sv.w, a);
            }
            acc[bb] = a;
        }
        if (half == 1) {
#pragma unroll
            for (int bb = 0; bb < 4; bb++) part[bb][d] = acc[bb];
        }
        __syncthreads();
        if (half == 0) {
#pragma unroll
            for (int bb = 0; bb < 4; bb++) {
                float o = acc[bb] + part[bb][d] + ab;
                o = (o > 0.f) ? o : expm1f(o);
                out[(size_t)(g * 4 + bb) * 64 + d] = o;
            }
        }
    }
}

extern "C" void kernel_launch(void* const* d_in, const int* in_sizes, int n_in,
                              void* d_out, int out_size) {
    const float* x_target = (const float*)d_in[0];
    const float* x_neigh  = (const float*)d_in[1];
    const float* align_w  = (const float*)d_in[2];
    const float* align_b  = (const float*)d_in[3];
    const float* attn1_w  = (const float*)d_in[4];
    const float* attn1_b  = (const float*)d_in[5];
    float* out = (float*)d_out;

    prep_kernel<<<9, 128>>>(align_w, align_b, attn1_w, attn1_b);

    void* wnp = nullptr; void* cbp = nullptr;
    cudaGetSymbolAddress(&wnp, WnP_g);
    cudaGetSymbolAddress(&cbp, CBP_g);
    cudaMemcpyToSymbolAsync(cWn,  wnp,     1024 * sizeof(float), 0, cudaMemcpyDeviceToDevice, 0);
    cudaMemcpyToSymbolAsync(cCB,  cbp,       16 * sizeof(float), 0, cudaMemcpyDeviceToDevice, 0);
    cudaMemcpyToSymbolAsync(cA2,  d_in[6],   16 * sizeof(float), 0, cudaMemcpyDeviceToDevice, 0);
    cudaMemcpyToSymbolAsync(cA2B, d_in[7],    1 * sizeof(float), 0, cudaMemcpyDeviceToDevice, 0);

    gat_kernel<<<GRID, 128>>>(x_target, x_neigh, align_w, align_b, out);
}

// round 7
// speedup vs baseline: 1.0867x; 1.0867x over previous
#include <cuda_runtime.h>
#include <math.h>

// GAT layer, algebraically folded + fissioned:
//  K1 prep : Wn = attn1_w[:,64:]@align_w, Wt = attn1_w[:,:64]@align_w,
//            cb = (attn1_w[:,:64]+attn1_w[:,64:])@align_b + attn1_b
//  K2 eb   : eb[b] = Wt @ x_t[b] + cb                     (65536 x 16)
//  K3 main : e_n = leaky(attn2 @ relu(Wn x_n + eb) + b2); a = softmax(e);
//            s[b] = sum_n a_n x_n                          (65536 x 64)
//  K4 out  : out = elu(align_w @ s + align_b)

#define GRID 1480
typedef unsigned long long ull;

__device__ float WnP_g[1024];
__device__ float WtP_g[1024];
__device__ float CBP_g[16];
__device__ float eb_g[65536 * 16];     // 4 MB scratch
__device__ float s_g[65536 * 64];      // 16 MB scratch

__device__ __forceinline__ ull splat2(float a) {
    ull r; asm("mov.b64 %0, {%1, %1};" : "=l"(r) : "f"(a)); return r;
}
__device__ __forceinline__ void fma2(ull& acc, ull a, ull b) {
    asm("fma.rn.f32x2 %0, %1, %2, %0;" : "+l"(acc) : "l"(a), "l"(b));
}
__device__ __forceinline__ float2 unpack2(ull v) {
    float2 r; asm("mov.b64 {%0, %1}, %2;" : "=f"(r.x), "=f"(r.y) : "l"(v)); return r;
}
__device__ __forceinline__ void lds_v2u64(ull& a, ull& b, unsigned addr) {
    asm volatile("ld.shared.v2.b64 {%0, %1}, [%2];" : "=l"(a), "=l"(b) : "r"(addr));
}

// ---------------- K1: fold weights ----------------
__global__ void prep_kernel(const float* __restrict__ align_w,
                            const float* __restrict__ align_b,
                            const float* __restrict__ a1w,
                            const float* __restrict__ a1b) {
    int idx = blockIdx.x * blockDim.x + threadIdx.x;
    if (idx < 1024) {
        int c = idx >> 4, h = idx & 15;
        float st = 0.f, sn = 0.f;
        for (int d = 0; d < 64; d++) {
            float aw = align_w[d * 64 + c];
            st = fmaf(a1w[h * 128 + d],      aw, st);
            sn = fmaf(a1w[h * 128 + 64 + d], aw, sn);
        }
        WtP_g[c * 16 + h] = st;
        WnP_g[c * 16 + h] = sn;
    } else if (idx < 1040) {
        int h = idx - 1024;
        float s = 0.f;
        for (int d = 0; d < 64; d++)
            s += (a1w[h * 128 + d] + a1w[h * 128 + 64 + d]) * align_b[d];
        CBP_g[h] = s + a1b[h];
    }
}

// ---------------- K2: eb[b] = Wt @ x_t[b] + cb ----------------
__global__ __launch_bounds__(128) void eb_kernel(const float* __restrict__ xt) {
    __shared__ float xs[512];
    __shared__ float wt[1024];
    __shared__ float cbs[16];
    const int tid = threadIdx.x;
    for (int i = tid; i < 1024; i += 128) wt[i] = WtP_g[i];
    if (tid < 16) cbs[tid] = CBP_g[tid];
    const int b0 = blockIdx.x * 8;
    for (int i = tid; i < 512; i += 128) xs[i] = xt[(size_t)b0 * 64 + i];
    __syncthreads();
    const int bl = tid >> 4, h = tid & 15;
    float acc = 0.f;
#pragma unroll 8
    for (int c = 0; c < 64; c++) acc = fmaf(xs[bl * 64 + c], wt[c * 16 + h], acc);
    eb_g[(size_t)(b0 + bl) * 16 + h] = acc + cbs[h];
}

// ---------------- K3: main (attention + weighted sum) ----------------
__global__ __launch_bounds__(128, 5)
void gat_kernel(const float* __restrict__ xn,
                const float* __restrict__ a2w,
                const float* __restrict__ a2b) {
    __shared__ __align__(16) float4 xs4[4][576];   // 36 rows x 16 chunks (row 35 = zero pad)
    __shared__ __align__(16) float  Wn_s[1024];
    __shared__ __align__(8)  float  a_s[4][36];

    const int tid  = threadIdx.x;
    const int wid  = tid >> 5;
    const int lane = tid & 31;
    const int nI   = lane & 7;
    const int hI   = lane >> 3;
    const int cq   = lane & 15;
    const int rh   = lane >> 4;

    for (int i = tid; i < 1024; i += 128) Wn_s[i] = WnP_g[i];
    if (lane < 16) xs4[wid][560 + lane] = make_float4(0.f, 0.f, 0.f, 0.f);  // zero row 35

    float4 a2v = __ldg((const float4*)a2w + hI);
    const float a2r0 = a2v.x, a2r1 = a2v.y, a2r2 = a2v.z, a2r3 = a2v.w;
    const float b2 = __ldg(a2b);
    const unsigned wn_base = (unsigned)__cvta_generic_to_shared(Wn_s);

    __syncthreads();

    for (int g = blockIdx.x; g < 16384; g += GRID) {
        const int b = g * 4 + wid;
        float4* xw4 = xs4[wid];

        // ---- phase 1: stage x_neigh (35 rows), float4 + XOR swizzle
        {
            const float4* src4 = (const float4*)xn + (size_t)b * 560;
#pragma unroll
            for (int k = 0; k < 18; k++) {
                int idx = k * 32 + lane;
                if (idx < 560) {
                    int row = idx >> 4, c4 = idx & 15;
                    xw4[row * 16 + (c4 ^ (row & 7))] = src4[idx];
                }
            }
        }
        __syncwarp();

        // ---- phase 2: u[j][h0..h3] = (Wn @ x_row)[4hI..], rows nI + 8j
        ull u2[5][2];
#pragma unroll
        for (int j = 0; j < 5; j++) { u2[j][0] = 0ull; u2[j][1] = 0ull; }
        const bool has2 = (nI < 3);
        const int row4 = has2 ? (nI + 32) : 35;   // row 35 is zeroed pad

#pragma unroll 4
        for (int p4 = 0; p4 < 16; p4++) {
            ull wl[4], wh[4];
#pragma unroll
            for (int cc = 0; cc < 4; cc++)
                lds_v2u64(wl[cc], wh[cc], wn_base + ((4 * p4 + cc) * 16 + 4 * hI) * 4);
#pragma unroll
            for (int j = 0; j < 5; j++) {
                int row = (j < 4) ? (nI + 8 * j) : row4;
                float4 xv = xw4[row * 16 + (p4 ^ (row & 7))];
                ull a0 = splat2(xv.x), a1 = splat2(xv.y);
                ull a2_ = splat2(xv.z), a3 = splat2(xv.w);
                fma2(u2[j][0], a0,  wl[0]); fma2(u2[j][1], a0,  wh[0]);
                fma2(u2[j][0], a1,  wl[1]); fma2(u2[j][1], a1,  wh[1]);
                fma2(u2[j][0], a2_, wl[2]); fma2(u2[j][1], a2_, wh[2]);
                fma2(u2[j][0], a3,  wl[3]); fma2(u2[j][1], a3,  wh[3]);
            }
        }

        // ---- eb (precomputed target contribution incl. bias)
        float4 ebv = __ldg((const float4*)eb_g + (size_t)b * 4 + hI);

        // ---- phase 3: e, leaky relu, softmax over n
        float e[5];
#pragma unroll
        for (int j = 0; j < 5; j++) {
            float2 lo = unpack2(u2[j][0]), hi = unpack2(u2[j][1]);
            float pe;
            pe =      a2r0 * fmaxf(lo.x + ebv.x, 0.f);
            pe = fmaf(a2r1,  fmaxf(lo.y + ebv.y, 0.f), pe);
            pe = fmaf(a2r2,  fmaxf(hi.x + ebv.z, 0.f), pe);
            pe = fmaf(a2r3,  fmaxf(hi.y + ebv.w, 0.f), pe);
            pe += __shfl_xor_sync(0xffffffffu, pe, 8);
            pe += __shfl_xor_sync(0xffffffffu, pe, 16);
            float ev = pe + b2;
            e[j] = ev > 0.f ? ev : 0.2f * ev;
        }
        if (!has2) e[4] = -INFINITY;

        float mx = e[0];
#pragma unroll
        for (int j = 1; j < 5; j++) mx = fmaxf(mx, e[j]);
#pragma unroll
        for (int m = 1; m <= 4; m <<= 1) mx = fmaxf(mx, __shfl_xor_sync(0xffffffffu, mx, m));

        float ax[5]; float sum = 0.f;
#pragma unroll
        for (int j = 0; j < 5; j++) { ax[j] = __expf(e[j] - mx); sum += ax[j]; }
#pragma unroll
        for (int m = 1; m <= 4; m <<= 1) sum += __shfl_xor_sync(0xffffffffu, sum, m);
        float rinv = 1.0f / sum;

        if (hI == 0) {
#pragma unroll
            for (int j = 0; j < 4; j++) a_s[wid][nI + 8 * j] = ax[j] * rinv;
            if (has2) a_s[wid][nI + 32] = ax[4] * rinv;
            if (nI == 3) a_s[wid][35] = 0.f;   // pad row weight
        }
        __syncwarp();

        // ---- phase 4: s[c] = sum_n a_n x_n[c]; lane=(cq,rh): 4 c x 18 rows
        float2 ap[9];
#pragma unroll
        for (int i = 0; i < 9; i++) ap[i] = *(const float2*)&a_s[wid][rh * 18 + 2 * i];

        float4 acc = make_float4(0.f, 0.f, 0.f, 0.f);
#pragma unroll
        for (int q = 0; q < 18; q++) {
            int row = rh * 18 + q;                 // row 35 contributes 0 (a=0, x=0)
            float a = (q & 1) ? ap[q >> 1].y : ap[q >> 1].x;
            float4 xv = xw4[row * 16 + (cq ^ (row & 7))];
            acc.x = fmaf(a, xv.x, acc.x);
            acc.y = fmaf(a, xv.y, acc.y);
            acc.z = fmaf(a, xv.z, acc.z);
            acc.w = fmaf(a, xv.w, acc.w);
        }
        acc.x += __shfl_xor_sync(0xffffffffu, acc.x, 16);
        acc.y += __shfl_xor_sync(0xffffffffu, acc.y, 16);
        acc.z += __shfl_xor_sync(0xffffffffu, acc.z, 16);
        acc.w += __shfl_xor_sync(0xffffffffu, acc.w, 16);
        if (rh == 0)
            *((float4*)(s_g + (size_t)b * 64) + cq) = acc;
        __syncwarp();
    }
}

// ---------------- K4: out = elu(align_w @ s + align_b) ----------------
__global__ __launch_bounds__(128, 8)
void out_kernel(const float* __restrict__ aw,
                const float* __restrict__ abv,
                float* __restrict__ out) {
    const int tid  = threadIdx.x;
    const int d    = tid >> 1;        // output channel (0..63)
    const int half = tid & 1;         // c-half, reduced via shfl 1

    float ar[32];
#pragma unroll
    for (int i = 0; i < 32; i++) ar[i] = aw[d * 64 + half * 32 + i];
    const float ab = abv[d];

    for (int g = blockIdx.x; g < 16384; g += 2048) {
#pragma unroll
        for (int bb = 0; bb < 4; bb++) {
            size_t b = (size_t)g * 4 + bb;
            const float4* sp = (const float4*)(s_g + b * 64) + half * 8;
            float a = 0.f;
#pragma unroll
            for (int i = 0; i < 8; i++) {
                float4 sv = __ldg(sp + i);
                a = fmaf(ar[4 * i + 0], sv.x, a);
                a = fmaf(ar[4 * i + 1], sv.y, a);
                a = fmaf(ar[4 * i + 2], sv.z, a);
                a = fmaf(ar[4 * i + 3], sv.w, a);
            }
            a += __shfl_xor_sync(0xffffffffu, a, 1);
            if (half == 0) {
                float o = a + ab;
                o = (o > 0.f) ? o : expm1f(o);
                out[b * 64 + d] = o;
            }
        }
    }
}

extern "C" void kernel_launch(void* const* d_in, const int* in_sizes, int n_in,
                              void* d_out, int out_size) {
    const float* x_target = (const float*)d_in[0];
    const float* x_neigh  = (const float*)d_in[1];
    const float* align_w  = (const float*)d_in[2];
    const float* align_b  = (const float*)d_in[3];
    const float* attn1_w  = (const float*)d_in[4];
    const float* attn1_b  = (const float*)d_in[5];
    const float* attn2_w  = (const float*)d_in[6];
    const float* attn2_b  = (const float*)d_in[7];
    float* out = (float*)d_out;

    prep_kernel<<<9, 128>>>(align_w, align_b, attn1_w, attn1_b);
    eb_kernel<<<8192, 128>>>(x_target);
    gat_kernel<<<GRID, 128>>>(x_neigh, attn2_w, attn2_b);
    out_kernel<<<2048, 128>>>(align_w, align_b, out);
}

// round 8
// speedup vs baseline: 1.4866x; 1.3681x over previous
#include <cuda_runtime.h>
#include <math.h>

// GAT layer, algebraically folded + fissioned:
//  K1 prep : Wn = attn1_w[:,64:]@align_w, Wt = attn1_w[:,:64]@align_w,
//            cb = (attn1_w[:,:64]+attn1_w[:,64:])@align_b + attn1_b
//  K2 eb   : eb[b] = Wt @ x_t[b] + cb                     (65536 x 16)
//  K3 main : e_n = leaky(attn2 @ relu(Wn x_n + eb) + b2); a = softmax(e);
//            s[b] = sum_n a_n x_n                          (65536 x 64)
//  K4 out  : out = elu(align_w @ s + align_b)   [smem-tiled GEMM, f32x2]

#define GRID 1480
typedef unsigned long long ull;

__device__ float WnP_g[1024];
__device__ float WtP_g[1024];
__device__ float CBP_g[16];
__device__ float eb_g[65536 * 16];     // 4 MB scratch
__device__ float s_g[65536 * 64];      // 16 MB scratch

__device__ __forceinline__ ull splat2(float a) {
    ull r; asm("mov.b64 %0, {%1, %1};" : "=l"(r) : "f"(a)); return r;
}
__device__ __forceinline__ void fma2(ull& acc, ull a, ull b) {
    asm("fma.rn.f32x2 %0, %1, %2, %0;" : "+l"(acc) : "l"(a), "l"(b));
}
__device__ __forceinline__ float2 unpack2(ull v) {
    float2 r; asm("mov.b64 {%0, %1}, %2;" : "=f"(r.x), "=f"(r.y) : "l"(v)); return r;
}
__device__ __forceinline__ void lds_v2u64(ull& a, ull& b, unsigned addr) {
    asm volatile("ld.shared.v2.b64 {%0, %1}, [%2];" : "=l"(a), "=l"(b) : "r"(addr));
}

// ---------------- K1: fold weights ----------------
__global__ void prep_kernel(const float* __restrict__ align_w,
                            const float* __restrict__ align_b,
                            const float* __restrict__ a1w,
                            const float* __restrict__ a1b) {
    int idx = blockIdx.x * blockDim.x + threadIdx.x;
    if (idx < 1024) {
        int c = idx >> 4, h = idx & 15;
        float st = 0.f, sn = 0.f;
        for (int d = 0; d < 64; d++) {
            float aw = align_w[d * 64 + c];
            st = fmaf(a1w[h * 128 + d],      aw, st);
            sn = fmaf(a1w[h * 128 + 64 + d], aw, sn);
        }
        WtP_g[c * 16 + h] = st;
        WnP_g[c * 16 + h] = sn;
    } else if (idx < 1040) {
        int h = idx - 1024;
        float s = 0.f;
        for (int d = 0; d < 64; d++)
            s += (a1w[h * 128 + d] + a1w[h * 128 + 64 + d]) * align_b[d];
        CBP_g[h] = s + a1b[h];
    }
}

// ---------------- K2: eb[b] = Wt @ x_t[b] + cb ----------------
__global__ __launch_bounds__(128) void eb_kernel(const float* __restrict__ xt) {
    __shared__ float xs[512];
    __shared__ float wt[1024];
    __shared__ float cbs[16];
    const int tid = threadIdx.x;
    for (int i = tid; i < 1024; i += 128) wt[i] = WtP_g[i];
    if (tid < 16) cbs[tid] = CBP_g[tid];
    const int b0 = blockIdx.x * 8;
    for (int i = tid; i < 512; i += 128) xs[i] = xt[(size_t)b0 * 64 + i];
    __syncthreads();
    const int bl = tid >> 4, h = tid & 15;
    float acc = 0.f;
#pragma unroll 8
    for (int c = 0; c < 64; c++) acc = fmaf(xs[bl * 64 + c], wt[c * 16 + h], acc);
    eb_g[(size_t)(b0 + bl) * 16 + h] = acc + cbs[h];
}

// ---------------- K3: main (attention + weighted sum) ----------------
__global__ __launch_bounds__(128, 5)
void gat_kernel(const float* __restrict__ xn,
                const float* __restrict__ a2w,
                const float* __restrict__ a2b) {
    __shared__ __align__(16) float4 xs4[4][576];   // 36 rows x 16 chunks (row 35 = zero pad)
    __shared__ __align__(16) float  Wn_s[1024];
    __shared__ __align__(8)  float  a_s[4][36];

    const int tid  = threadIdx.x;
    const int wid  = tid >> 5;
    const int lane = tid & 31;
    const int nI   = lane & 7;
    const int hI   = lane >> 3;
    const int cq   = lane & 15;
    const int rh   = lane >> 4;

    for (int i = tid; i < 1024; i += 128) Wn_s[i] = WnP_g[i];
    if (lane < 16) xs4[wid][560 + lane] = make_float4(0.f, 0.f, 0.f, 0.f);  // zero row 35

    float4 a2v = __ldg((const float4*)a2w + hI);
    const float a2r0 = a2v.x, a2r1 = a2v.y, a2r2 = a2v.z, a2r3 = a2v.w;
    const float b2 = __ldg(a2b);
    const unsigned wn_base = (unsigned)__cvta_generic_to_shared(Wn_s);

    __syncthreads();

    for (int g = blockIdx.x; g < 16384; g += GRID) {
        const int b = g * 4 + wid;
        float4* xw4 = xs4[wid];

        // ---- phase 1: stage x_neigh (35 rows), float4 + XOR swizzle
        {
            const float4* src4 = (const float4*)xn + (size_t)b * 560;
#pragma unroll
            for (int k = 0; k < 18; k++) {
                int idx = k * 32 + lane;
                if (idx < 560) {
                    int row = idx >> 4, c4 = idx & 15;
                    xw4[row * 16 + (c4 ^ (row & 7))] = src4[idx];
                }
            }
        }
        __syncwarp();

        // ---- phase 2: u[j][h0..h3] = (Wn @ x_row)[4hI..], rows nI + 8j
        ull u2[5][2];
#pragma unroll
        for (int j = 0; j < 5; j++) { u2[j][0] = 0ull; u2[j][1] = 0ull; }
        const bool has2 = (nI < 3);
        const int row4 = has2 ? (nI + 32) : 35;   // row 35 is zeroed pad

#pragma unroll 4
        for (int p4 = 0; p4 < 16; p4++) {
            ull wl[4], wh[4];
#pragma unroll
            for (int cc = 0; cc < 4; cc++)
                lds_v2u64(wl[cc], wh[cc], wn_base + ((4 * p4 + cc) * 16 + 4 * hI) * 4);
#pragma unroll
            for (int j = 0; j < 5; j++) {
                int row = (j < 4) ? (nI + 8 * j) : row4;
                float4 xv = xw4[row * 16 + (p4 ^ (row & 7))];
                ull a0 = splat2(xv.x), a1 = splat2(xv.y);
                ull a2_ = splat2(xv.z), a3 = splat2(xv.w);
                fma2(u2[j][0], a0,  wl[0]); fma2(u2[j][1], a0,  wh[0]);
                fma2(u2[j][0], a1,  wl[1]); fma2(u2[j][1], a1,  wh[1]);
                fma2(u2[j][0], a2_, wl[2]); fma2(u2[j][1], a2_, wh[2]);
                fma2(u2[j][0], a3,  wl[3]); fma2(u2[j][1], a3,  wh[3]);
            }
        }

        // ---- eb (precomputed target contribution incl. bias)
        float4 ebv = __ldg((const float4*)eb_g + (size_t)b * 4 + hI);

        // ---- phase 3: e, leaky relu, softmax over n
        float e[5];
#pragma unroll
        for (int j = 0; j < 5; j++) {
            float2 lo = unpack2(u2[j][0]), hi = unpack2(u2[j][1]);
            float pe;
            pe =      a2r0 * fmaxf(lo.x + ebv.x, 0.f);
            pe = fmaf(a2r1,  fmaxf(lo.y + ebv.y, 0.f), pe);
            pe = fmaf(a2r2,  fmaxf(hi.x + ebv.z, 0.f), pe);
            pe = fmaf(a2r3,  fmaxf(hi.y + ebv.w, 0.f), pe);
            pe += __shfl_xor_sync(0xffffffffu, pe, 8);
            pe += __shfl_xor_sync(0xffffffffu, pe, 16);
            float ev = pe + b2;
            e[j] = ev > 0.f ? ev : 0.2f * ev;
        }
        if (!has2) e[4] = -INFINITY;

        float mx = e[0];
#pragma unroll
        for (int j = 1; j < 5; j++) mx = fmaxf(mx, e[j]);
#pragma unroll
        for (int m = 1; m <= 4; m <<= 1) mx = fmaxf(mx, __shfl_xor_sync(0xffffffffu, mx, m));

        float ax[5]; float sum = 0.f;
#pragma unroll
        for (int j = 0; j < 5; j++) { ax[j] = __expf(e[j] - mx); sum += ax[j]; }
#pragma unroll
        for (int m = 1; m <= 4; m <<= 1) sum += __shfl_xor_sync(0xffffffffu, sum, m);
        float rinv = 1.0f / sum;

        if (hI == 0) {
#pragma unroll
            for (int j = 0; j < 4; j++) a_s[wid][nI + 8 * j] = ax[j] * rinv;
            if (has2) a_s[wid][nI + 32] = ax[4] * rinv;
            if (nI == 3) a_s[wid][35] = 0.f;   // pad row weight
        }
        __syncwarp();

        // ---- phase 4: s[c] = sum_n a_n x_n[c]; lane=(cq,rh): 4 c x 18 rows
        float2 ap[9];
#pragma unroll
        for (int i = 0; i < 9; i++) ap[i] = *(const float2*)&a_s[wid][rh * 18 + 2 * i];

        float4 acc = make_float4(0.f, 0.f, 0.f, 0.f);
#pragma unroll
        for (int q = 0; q < 18; q++) {
            int row = rh * 18 + q;                 // row 35 contributes 0 (a=0, x=0)
            float a = (q & 1) ? ap[q >> 1].y : ap[q >> 1].x;
            float4 xv = xw4[row * 16 + (cq ^ (row & 7))];
            acc.x = fmaf(a, xv.x, acc.x);
            acc.y = fmaf(a, xv.y, acc.y);
            acc.z = fmaf(a, xv.z, acc.z);
            acc.w = fmaf(a, xv.w, acc.w);
        }
        acc.x += __shfl_xor_sync(0xffffffffu, acc.x, 16);
        acc.y += __shfl_xor_sync(0xffffffffu, acc.y, 16);
        acc.z += __shfl_xor_sync(0xffffffffu, acc.z, 16);
        acc.w += __shfl_xor_sync(0xffffffffu, acc.w, 16);
        if (rh == 0)
            *((float4*)(s_g + (size_t)b * 64) + cq) = acc;
        __syncwarp();
    }
}

// ---------------- K4: out = elu(align_w @ s + align_b) ----------------
// Tiled GEMM: 1024 blocks x 256 threads, 64-batch tile per block.
// smem s tile [b][c] pitch 68, W^T [c][d] pitch 68. Thread = 4b x 4d micro-tile.
#define OPITCH 68
__global__ __launch_bounds__(256)
void out_kernel(const float* __restrict__ aw,
                const float* __restrict__ abv,
                float* __restrict__ out) {
    __shared__ __align__(16) float s_s[64 * OPITCH];
    __shared__ __align__(16) float w_t[64 * OPITCH];
    __shared__ float ab_s[64];

    const int tid = threadIdx.x;
    const int b0  = blockIdx.x * 64;

    // W^T: w_t[c][d] = aw[d*64+c]  (one-time; minor write conflicts OK)
#pragma unroll
    for (int k = 0; k < 16; k++) {
        int idx = k * 256 + tid;
        int d = idx >> 6, c = idx & 63;
        w_t[c * OPITCH + d] = aw[idx];
    }
    if (tid < 64) ab_s[tid] = abv[tid];

    // stage s tile, coalesced float4
#pragma unroll
    for (int k = 0; k < 4; k++) {
        int idx4 = k * 256 + tid;
        int bl = idx4 >> 4, c4 = idx4 & 15;
        *(float4*)&s_s[bl * OPITCH + c4 * 4] =
            ((const float4*)(s_g + (size_t)(b0 + bl) * 64))[c4];
    }
    __syncthreads();

    const int tx = tid & 15;     // d-group: d = 4*tx .. 4*tx+3
    const int ty = tid >> 4;     // b-group: b = 4*ty .. 4*ty+3

    ull acc2[4][2];
#pragma unroll
    for (int bi = 0; bi < 4; bi++) { acc2[bi][0] = 0ull; acc2[bi][1] = 0ull; }

#pragma unroll
    for (int cs = 0; cs < 16; cs++) {
        ull wv[4][2];
#pragma unroll
        for (int j = 0; j < 4; j++) {
            const float* wp = &w_t[(4 * cs + j) * OPITCH + 4 * tx];
            wv[j][0] = *(const ull*)&wp[0];
            wv[j][1] = *(const ull*)&wp[2];
        }
#pragma unroll
        for (int bi = 0; bi < 4; bi++) {
            float4 sv = *(const float4*)&s_s[(4 * ty + bi) * OPITCH + 4 * cs];
            ull a0 = splat2(sv.x), a1 = splat2(sv.y);
            ull a2 = splat2(sv.z), a3 = splat2(sv.w);
            fma2(acc2[bi][0], a0, wv[0][0]); fma2(acc2[bi][1], a0, wv[0][1]);
            fma2(acc2[bi][0], a1, wv[1][0]); fma2(acc2[bi][1], a1, wv[1][1]);
            fma2(acc2[bi][0], a2, wv[2][0]); fma2(acc2[bi][1], a2, wv[2][1]);
            fma2(acc2[bi][0], a3, wv[3][0]); fma2(acc2[bi][1], a3, wv[3][1]);
        }
    }

    float4 abv4 = *(const float4*)&ab_s[4 * tx];
#pragma unroll
    for (int bi = 0; bi < 4; bi++) {
        float2 lo = unpack2(acc2[bi][0]), hi = unpack2(acc2[bi][1]);
        float4 o;
        o.x = lo.x + abv4.x; o.x = (o.x > 0.f) ? o.x : expm1f(o.x);
        o.y = lo.y + abv4.y; o.y = (o.y > 0.f) ? o.y : expm1f(o.y);
        o.z = hi.x + abv4.z; o.z = (o.z > 0.f) ? o.z : expm1f(o.z);
        o.w = hi.y + abv4.w; o.w = (o.w > 0.f) ? o.w : expm1f(o.w);
        *(float4*)&out[(size_t)(b0 + 4 * ty + bi) * 64 + 4 * tx] = o;
    }
}

extern "C" void kernel_launch(void* const* d_in, const int* in_sizes, int n_in,
                              void* d_out, int out_size) {
    const float* x_target = (const float*)d_in[0];
    const float* x_neigh  = (const float*)d_in[1];
    const float* align_w  = (const float*)d_in[2];
    const float* align_b  = (const float*)d_in[3];
    const float* attn1_w  = (const float*)d_in[4];
    const float* attn1_b  = (const float*)d_in[5];
    const float* attn2_w  = (const float*)d_in[6];
    const float* attn2_b  = (const float*)d_in[7];
    float* out = (float*)d_out;

    prep_kernel<<<9, 128>>>(align_w, align_b, attn1_w, attn1_b);
    eb_kernel<<<8192, 128>>>(x_target);
    gat_kernel<<<GRID, 128>>>(x_neigh, attn2_w, attn2_b);
    out_kernel<<<1024, 256>>>(align_w, align_b, out);
}